// round 13
// baseline (speedup 1.0000x reference)
#include <cuda_runtime.h>
#include <cuda_fp16.h>
#include <math.h>
#include <stdint.h>

#define NN 50000
#define MP 50048          // NN padded to 128
#define DD 128
#define KK 32
#define TWO_D 256

// ---------------------------------------------------------------------------
// Global scratch
// ---------------------------------------------------------------------------
__device__ float g_wq[(size_t)NN * TWO_D];     // wq = [v|t] @ W.T
__device__ __half g_Whi16[TWO_D * TWO_D];      // fp16 hi of W
__device__ __half g_Wlo16[TWO_D * TWO_D];      // fp16 lo of W

// ---------------------------------------------------------------------------
// helpers
// ---------------------------------------------------------------------------
__device__ __forceinline__ uint32_t smem_u32(const void* p) {
    uint32_t a;
    asm("{ .reg .u64 t; cvta.to.shared.u64 t, %1; cvt.u32.u64 %0, t; }" : "=r"(a) : "l"(p));
    return a;
}
__device__ __forceinline__ void ldsm_x4(uint32_t* r, uint32_t addr) {
    asm volatile("ldmatrix.sync.aligned.m8n8.x4.shared.b16 {%0,%1,%2,%3}, [%4];"
                 : "=r"(r[0]), "=r"(r[1]), "=r"(r[2]), "=r"(r[3]) : "r"(addr));
}
__device__ __forceinline__ void mma16816h(float* d, const uint32_t* a, uint32_t b0, uint32_t b1) {
    asm volatile(
        "mma.sync.aligned.m16n8k16.row.col.f32.f16.f16.f32 "
        "{%0,%1,%2,%3}, {%4,%5,%6,%7}, {%8,%9}, {%0,%1,%2,%3};"
        : "+f"(d[0]), "+f"(d[1]), "+f"(d[2]), "+f"(d[3])
        : "r"(a[0]), "r"(a[1]), "r"(a[2]), "r"(a[3]), "r"(b0), "r"(b1));
}
__device__ __forceinline__ void cp16z(uint32_t saddr, const void* gaddr, uint32_t sz) {
    asm volatile("cp.async.cg.shared.global [%0], [%1], 16, %2;"
                 :: "r"(saddr), "l"(gaddr), "r"(sz));
}
__device__ __forceinline__ void cp16(uint32_t saddr, const void* gaddr) {
    asm volatile("cp.async.cg.shared.global [%0], [%1], 16;" :: "r"(saddr), "l"(gaddr));
}
__device__ __forceinline__ void cp_commit() {
    asm volatile("cp.async.commit_group;" ::: "memory");
}
__device__ __forceinline__ void gdc_launch_dependents() {
    asm volatile("griddepcontrol.launch_dependents;");
}
__device__ __forceinline__ void gdc_wait() {
    asm volatile("griddepcontrol.wait;" ::: "memory");
}

// ---------------------------------------------------------------------------
// Kernel 0: W -> fp16 hi/lo split (once; W is 256x256)
// ---------------------------------------------------------------------------
__global__ __launch_bounds__(256) void w_split(const float* __restrict__ W) {
    gdc_launch_dependents();   // let the GEMM start loading A immediately
    int i = blockIdx.x * blockDim.x + threadIdx.x;   // 16384 quads
    float4 x = *(const float4*)(W + (size_t)i * 4);
    __half2 h01 = __floats2half2_rn(x.x, x.y);
    __half2 h23 = __floats2half2_rn(x.z, x.w);
    float l0 = x.x - __half2float(__low2half(h01));
    float l1 = x.y - __half2float(__high2half(h01));
    float l2 = x.z - __half2float(__low2half(h23));
    float l3 = x.w - __half2float(__high2half(h23));
    __half2 g01 = __floats2half2_rn(l0, l1);
    __half2 g23 = __floats2half2_rn(l2, l3);
    *(uint2*)(g_Whi16 + (size_t)i * 4) = make_uint2(*(uint32_t*)&h01, *(uint32_t*)&h23);
    *(uint2*)(g_Wlo16 + (size_t)i * 4) = make_uint2(*(uint32_t*)&g01, *(uint32_t*)&g23);
}

// ---------------------------------------------------------------------------
// Kernel 1: fused GEMM  g_wq[m][j] = sum_k A[m][k]*W[j][k], A=[v_fea|t_emb].
// BM=128, BN=64, 8 warps (4x2). 8 k-chunks of 32.
//  - A: cp.async fp32 -> smem staging (2 bufs) -> in-kernel fp16 convert
//  - W: cp.async PRE-SPLIT fp16 hi/lo straight into the MMA buffers
//  - f16 buffers: 3 stages -> ONE __syncthreads per chunk
//  - 2 accumulating HMMA passes: A*Whi + A*Wlo
//  - PDL: A-loads of chunks 0,1 issued BEFORE griddepcontrol.wait (w_split
//    output only needed for the W loads).
// ---------------------------------------------------------------------------
#define ROWF 144                      // fp32 staging row: 128B + 16B pad
#define STGA_SZ (128 * ROWF)          // 18432
#define ROWB 80                       // fp16 row: 64B + 16B pad
#define ABUF_SZ (128 * ROWB)          // 10240
#define WBUF_SZ (64 * ROWB)           // 5120
#define STAGE_F16 (ABUF_SZ + 2 * WBUF_SZ)      // 20480
#define F16_BASE (2 * STGA_SZ)                 // 36864
#define GEMM_SMEM (F16_BASE + 3 * STAGE_F16)   // 98304

__device__ __forceinline__ void load_A(uint32_t sbase, int c, int m0,
                                       const float* __restrict__ v_fea,
                                       const float* __restrict__ t_emb, int tid) {
    const uint32_t stgA = sbase + (c & 1) * STGA_SZ;
    const float* asrc = (c < 4) ? v_fea : t_emb;
    const int col0 = (c & 3) * 32;
#pragma unroll
    for (int g = 0; g < 4; g++) {
        int idx = g * 256 + tid;
        int row = idx >> 3, seg = idx & 7;
        uint32_t szA = (m0 + row < NN) ? 16u : 0u;
        cp16z(stgA + row * ROWF + seg * 16,
              asrc + (size_t)(m0 + row) * DD + col0 + seg * 4, szA);
    }
}
__device__ __forceinline__ void load_W(uint32_t sbase, int c, int n0, int tid) {
    const uint32_t wH = sbase + F16_BASE + (c % 3) * STAGE_F16 + ABUF_SZ;
    const uint32_t wL = wH + WBUF_SZ;
    int row = tid >> 2, seg = tid & 3;      // 64 rows x 4 16B-segs
    cp16(wH + row * ROWB + seg * 16,
         g_Whi16 + (size_t)(n0 + row) * TWO_D + c * 32 + seg * 8);
    cp16(wL + row * ROWB + seg * 16,
         g_Wlo16 + (size_t)(n0 + row) * TWO_D + c * 32 + seg * 8);
}

__device__ __forceinline__ void convert_chunk(char* smemc, int c, int tid) {
    const char* stg = smemc + (c & 1) * STGA_SZ;
    char* af = smemc + F16_BASE + (c % 3) * STAGE_F16;
    const int row = tid >> 1;
    const int c0 = (tid & 1) * 16;
#pragma unroll
    for (int i = 0; i < 4; i++) {
        const int cc = c0 + i * 4;
        float4 x = *(const float4*)(stg + row * ROWF + cc * 4);
        __half2 h01 = __floats2half2_rn(x.x, x.y);
        __half2 h23 = __floats2half2_rn(x.z, x.w);
        *(uint2*)(af + row * ROWB + cc * 2) =
            make_uint2(*(uint32_t*)&h01, *(uint32_t*)&h23);
    }
}

__global__ void __launch_bounds__(256, 2) wq_gemm_fused(const float* __restrict__ v_fea,
                                                        const float* __restrict__ t_emb) {
    extern __shared__ char smem[];
    const uint32_t sbase = smem_u32(smem);
    const int tid = threadIdx.x;
    const int lane = tid & 31, w = tid >> 5;
    const int wm = w >> 1, wn = w & 1;
    const int m0 = blockIdx.y * 128;
    const int n0 = blockIdx.x * 64;

    float acc[2][4][4];
#pragma unroll
    for (int i = 0; i < 2; i++)
#pragma unroll
        for (int j = 0; j < 4; j++)
#pragma unroll
            for (int q = 0; q < 4; q++) acc[i][j][q] = 0.f;

    // prologue: A loads don't depend on w_split -> issue before the PDL wait
    load_A(sbase, 0, m0, v_fea, t_emb, tid);
    load_A(sbase, 1, m0, v_fea, t_emb, tid);
    gdc_wait();                               // g_Whi16/g_Wlo16 now valid
    load_W(sbase, 0, n0, tid);
    load_W(sbase, 1, n0, tid);
    cp_commit();                              // single group: A0,A1,W0,W1
    asm volatile("cp.async.wait_group 0;" ::: "memory");
    __syncthreads();
    convert_chunk(smem, 0, tid);
    gdc_launch_dependents();                  // let edge_attn CTAs spin up

    for (int c = 0; c < 8; c++) {
        if (c + 1 < 8)
            asm volatile("cp.async.wait_group 0;" ::: "memory");  // chunk c+1 resident
        __syncthreads();   // convert(c) visible; stage (c+2)%3 readers done
        if (c + 1 < 8) convert_chunk(smem, c + 1, tid);
        if (c + 2 < 8) {
            load_A(sbase, c + 2, m0, v_fea, t_emb, tid);
            load_W(sbase, c + 2, n0, tid);
            cp_commit();
        }

        const uint32_t aF = sbase + F16_BASE + (c % 3) * STAGE_F16;
        const uint32_t bH = aF + ABUF_SZ;
        const uint32_t bL = bH + WBUF_SZ;

#pragma unroll
        for (int ks = 0; ks < 2; ks++) {
            uint32_t afr[2][4], bfh[2][4], bfl[2][4];
#pragma unroll
            for (int mi = 0; mi < 2; mi++) {
                int row = wm * 32 + mi * 16 + (lane & 15);
                uint32_t o = row * ROWB + ks * 32 + ((lane >> 4) << 4);
                ldsm_x4(afr[mi], aF + o);
            }
#pragma unroll
            for (int nj2 = 0; nj2 < 2; nj2++) {
                int row = wn * 32 + nj2 * 16 + (lane & 15);
                uint32_t o = row * ROWB + ks * 32 + ((lane >> 4) << 4);
                ldsm_x4(bfh[nj2], bH + o);
                ldsm_x4(bfl[nj2], bL + o);
            }
#pragma unroll
            for (int mi = 0; mi < 2; mi++)
#pragma unroll
                for (int nj = 0; nj < 4; nj++) {
                    uint32_t bh0 = bfh[nj >> 1][nj & 1], bh1 = bfh[nj >> 1][2 + (nj & 1)];
                    uint32_t bl0 = bfl[nj >> 1][nj & 1], bl1 = bfl[nj >> 1][2 + (nj & 1)];
                    mma16816h(acc[mi][nj], afr[mi], bh0, bh1);   // A * Whi
                    mma16816h(acc[mi][nj], afr[mi], bl0, bl1);   // A * Wlo
                }
        }
    }

    // epilogue
    const int gid = lane >> 2, tig = lane & 3;
#pragma unroll
    for (int mi = 0; mi < 2; mi++) {
        int mrow = m0 + wm * 32 + mi * 16 + gid;
#pragma unroll
        for (int nj = 0; nj < 4; nj++) {
            int col = n0 + wn * 32 + nj * 8 + tig * 2;
            if (mrow < NN)
                *(float2*)(g_wq + (size_t)mrow * TWO_D + col) =
                    make_float2(acc[mi][nj][0], acc[mi][nj][1]);
            if (mrow + 8 < NN)
                *(float2*)(g_wq + (size_t)(mrow + 8) * TWO_D + col) =
                    make_float2(acc[mi][nj][2], acc[mi][nj][3]);
        }
    }
}

// ---------------------------------------------------------------------------
// Kernel 2: edge attention (R7/R10 body) + PDL wait at entry.
// griddepcontrol.wait returns only after the GEMM's g_wq stores are visible;
// as a plain launch it is a no-op and stream order provides the guarantee.
// ---------------------------------------------------------------------------
__global__ __launch_bounds__(256) void edge_attn(const float* __restrict__ v_fea,
                                                 const float* __restrict__ t_emb,
                                                 const int* __restrict__ ef,
                                                 float* __restrict__ out) {
    gdc_wait();

    const int warp = (blockIdx.x * blockDim.x + threadIdx.x) >> 5;
    const int lane = threadIdx.x & 31;
    if (warp >= NN) return;

    const float* wqr = g_wq + (size_t)warp * TWO_D;
    const float4 wqa = *(const float4*)(wqr + lane * 4);
    const float4 wqb = *(const float4*)(wqr + DD + lane * 4);

    const int e_mine = ef[(size_t)warp * KK + lane];

    float m1 = -INFINITY, s1 = 0.f;
    float m2 = -INFINITY, s2 = 0.f;
    float4 a1 = make_float4(0.f, 0.f, 0.f, 0.f);
    float4 a2 = make_float4(0.f, 0.f, 0.f, 0.f);

#pragma unroll 2
    for (int k = 0; k < KK; k += 2) {
        int e1 = __shfl_sync(0xffffffffu, e_mine, k);
        int e2 = __shfl_sync(0xffffffffu, e_mine, k + 1);
        const float4 v1 = *(const float4*)(v_fea + (size_t)e1 * DD + lane * 4);
        const float4 t1 = *(const float4*)(t_emb + (size_t)e1 * DD + lane * 4);
        const float4 v2 = *(const float4*)(v_fea + (size_t)e2 * DD + lane * 4);
        const float4 t2 = *(const float4*)(t_emb + (size_t)e2 * DD + lane * 4);

        float p1 = v1.x * wqa.x + v1.y * wqa.y + v1.z * wqa.z + v1.w * wqa.w
                 + t1.x * wqb.x + t1.y * wqb.y + t1.z * wqb.z + t1.w * wqb.w;
        float p2 = v2.x * wqa.x + v2.y * wqa.y + v2.z * wqa.z + v2.w * wqa.w
                 + t2.x * wqb.x + t2.y * wqb.y + t2.z * wqb.z + t2.w * wqb.w;
        p1 += __shfl_xor_sync(0xffffffffu, p1, 16);
        p2 += __shfl_xor_sync(0xffffffffu, p2, 16);
        p1 += __shfl_xor_sync(0xffffffffu, p1, 8);
        p2 += __shfl_xor_sync(0xffffffffu, p2, 8);
        p1 += __shfl_xor_sync(0xffffffffu, p1, 4);
        p2 += __shfl_xor_sync(0xffffffffu, p2, 4);
        p1 += __shfl_xor_sync(0xffffffffu, p1, 2);
        p2 += __shfl_xor_sync(0xffffffffu, p2, 2);
        p1 += __shfl_xor_sync(0xffffffffu, p1, 1);
        p2 += __shfl_xor_sync(0xffffffffu, p2, 1);

        float mn1 = fmaxf(m1, p1);
        float c1 = __expf(m1 - mn1);
        float w1 = __expf(p1 - mn1);
        s1 = s1 * c1 + w1;
        a1.x = a1.x * c1 + w1 * v1.x;
        a1.y = a1.y * c1 + w1 * v1.y;
        a1.z = a1.z * c1 + w1 * v1.z;
        a1.w = a1.w * c1 + w1 * v1.w;
        m1 = mn1;

        float mn2 = fmaxf(m2, p2);
        float c2 = __expf(m2 - mn2);
        float w2 = __expf(p2 - mn2);
        s2 = s2 * c2 + w2;
        a2.x = a2.x * c2 + w2 * v2.x;
        a2.y = a2.y * c2 + w2 * v2.y;
        a2.z = a2.z * c2 + w2 * v2.z;
        a2.w = a2.w * c2 + w2 * v2.w;
        m2 = mn2;
    }

    float mn = fmaxf(m1, m2);
    float c1 = __expf(m1 - mn), c2 = __expf(m2 - mn);
    float s = s1 * c1 + s2 * c2;
    const float inv = 1.f / s;
    float4 o;
    o.x = (a1.x * c1 + a2.x * c2) * inv;
    o.y = (a1.y * c1 + a2.y * c2) * inv;
    o.z = (a1.z * c1 + a2.z * c2) * inv;
    o.w = (a1.w * c1 + a2.w * c2) * inv;
    *(float4*)(out + (size_t)warp * DD + lane * 4) = o;
}

// ---------------------------------------------------------------------------
extern "C" void kernel_launch(void* const* d_in, const int* in_sizes, int n_in,
                              void* d_out, int out_size) {
    const float* v_fea = (const float*)d_in[0];
    const float* t_emb = (const float*)d_in[1];
    const int* ef = (const int*)d_in[2];
    const float* W = (const float*)d_in[3];
    float* out = (float*)d_out;

    cudaFuncSetAttribute(wq_gemm_fused, cudaFuncAttributeMaxDynamicSharedMemorySize, GEMM_SMEM);

    w_split<<<TWO_D * TWO_D / 4 / 256, 256>>>(W);

    // GEMM as PDL-dependent of w_split
    {
        cudaLaunchConfig_t cfg = {};
        cfg.gridDim = dim3(TWO_D / 64, MP / 128, 1);
        cfg.blockDim = dim3(256, 1, 1);
        cfg.dynamicSmemBytes = GEMM_SMEM;
        cudaLaunchAttribute at[1];
        at[0].id = cudaLaunchAttributeProgrammaticStreamSerialization;
        at[0].val.programmaticStreamSerializationAllowed = 1;
        cfg.attrs = at;
        cfg.numAttrs = 1;
        cudaError_t e = cudaLaunchKernelEx(&cfg, wq_gemm_fused, v_fea, t_emb);
        if (e != cudaSuccess) {
            cudaGetLastError();
            wq_gemm_fused<<<dim3(TWO_D / 64, MP / 128), 256, GEMM_SMEM>>>(v_fea, t_emb);
        }
    }

    // edge as PDL-dependent of the GEMM
    {
        const int grid2 = (NN + 7) / 8;
        cudaLaunchConfig_t cfg = {};
        cfg.gridDim = dim3(grid2, 1, 1);
        cfg.blockDim = dim3(256, 1, 1);
        cfg.dynamicSmemBytes = 0;
        cudaLaunchAttribute at[1];
        at[0].id = cudaLaunchAttributeProgrammaticStreamSerialization;
        at[0].val.programmaticStreamSerializationAllowed = 1;
        cfg.attrs = at;
        cfg.numAttrs = 1;
        cudaError_t e = cudaLaunchKernelEx(&cfg, edge_attn, v_fea, t_emb, ef, out);
        if (e != cudaSuccess) {
            cudaGetLastError();
            edge_attn<<<grid2, 256>>>(v_fea, t_emb, ef, out);
        }
    }
}

// round 14
// speedup vs baseline: 1.0138x; 1.0138x over previous
#include <cuda_runtime.h>
#include <cuda_fp16.h>
#include <math.h>
#include <stdint.h>

#define NN 50000
#define MP 50048          // NN padded to 128
#define DD 128
#define KK 32
#define TWO_D 256

// ---------------------------------------------------------------------------
// Global scratch
// ---------------------------------------------------------------------------
__device__ float g_wq[(size_t)NN * TWO_D];     // wq = [v|t] @ W.T
__device__ __half g_Whi16[TWO_D * TWO_D];      // fp16 hi of W
__device__ __half g_Wlo16[TWO_D * TWO_D];      // fp16 lo of W

// ---------------------------------------------------------------------------
// helpers
// ---------------------------------------------------------------------------
__device__ __forceinline__ uint32_t smem_u32(const void* p) {
    uint32_t a;
    asm("{ .reg .u64 t; cvta.to.shared.u64 t, %1; cvt.u32.u64 %0, t; }" : "=r"(a) : "l"(p));
    return a;
}
__device__ __forceinline__ void ldsm_x4(uint32_t* r, uint32_t addr) {
    asm volatile("ldmatrix.sync.aligned.m8n8.x4.shared.b16 {%0,%1,%2,%3}, [%4];"
                 : "=r"(r[0]), "=r"(r[1]), "=r"(r[2]), "=r"(r[3]) : "r"(addr));
}
__device__ __forceinline__ void mma16816h(float* d, const uint32_t* a, uint32_t b0, uint32_t b1) {
    asm volatile(
        "mma.sync.aligned.m16n8k16.row.col.f32.f16.f16.f32 "
        "{%0,%1,%2,%3}, {%4,%5,%6,%7}, {%8,%9}, {%0,%1,%2,%3};"
        : "+f"(d[0]), "+f"(d[1]), "+f"(d[2]), "+f"(d[3])
        : "r"(a[0]), "r"(a[1]), "r"(a[2]), "r"(a[3]), "r"(b0), "r"(b1));
}
__device__ __forceinline__ void cp16z(uint32_t saddr, const void* gaddr, uint32_t sz) {
    asm volatile("cp.async.cg.shared.global [%0], [%1], 16, %2;"
                 :: "r"(saddr), "l"(gaddr), "r"(sz));
}
__device__ __forceinline__ void cp16(uint32_t saddr, const void* gaddr) {
    asm volatile("cp.async.cg.shared.global [%0], [%1], 16;" :: "r"(saddr), "l"(gaddr));
}
__device__ __forceinline__ void cp_commit() {
    asm volatile("cp.async.commit_group;" ::: "memory");
}

// ---------------------------------------------------------------------------
// Kernel 0: W -> fp16 hi/lo split (once; W is 256x256)
// ---------------------------------------------------------------------------
__global__ __launch_bounds__(256) void w_split(const float* __restrict__ W) {
    int i = blockIdx.x * blockDim.x + threadIdx.x;   // 16384 quads
    float4 x = *(const float4*)(W + (size_t)i * 4);
    __half2 h01 = __floats2half2_rn(x.x, x.y);
    __half2 h23 = __floats2half2_rn(x.z, x.w);
    float l0 = x.x - __half2float(__low2half(h01));
    float l1 = x.y - __half2float(__high2half(h01));
    float l2 = x.z - __half2float(__low2half(h23));
    float l3 = x.w - __half2float(__high2half(h23));
    __half2 g01 = __floats2half2_rn(l0, l1);
    __half2 g23 = __floats2half2_rn(l2, l3);
    *(uint2*)(g_Whi16 + (size_t)i * 4) = make_uint2(*(uint32_t*)&h01, *(uint32_t*)&h23);
    *(uint2*)(g_Wlo16 + (size_t)i * 4) = make_uint2(*(uint32_t*)&g01, *(uint32_t*)&g23);
}

// ---------------------------------------------------------------------------
// Kernel 1: fused GEMM (EXACT R12): g_wq[m][j] = sum_k A[m][k]*W[j][k].
// BM=128, BN=64, 8 warps (4x2). 8 k-chunks of 32. 3-stage f16 buffers,
// one __syncthreads per chunk, W pre-split, 2 HMMA passes.
// ---------------------------------------------------------------------------
#define ROWF 144                      // fp32 staging row: 128B + 16B pad
#define STGA_SZ (128 * ROWF)          // 18432
#define ROWB 80                       // fp16 row: 64B + 16B pad
#define ABUF_SZ (128 * ROWB)          // 10240
#define WBUF_SZ (64 * ROWB)           // 5120
#define STAGE_F16 (ABUF_SZ + 2 * WBUF_SZ)      // 20480
#define F16_BASE (2 * STGA_SZ)                 // 36864
#define GEMM_SMEM (F16_BASE + 3 * STAGE_F16)   // 98304

__device__ __forceinline__ void load_chunk(uint32_t sbase, int c, int m0, int n0,
                                           const float* __restrict__ v_fea,
                                           const float* __restrict__ t_emb, int tid) {
    const uint32_t stgA = sbase + (c & 1) * STGA_SZ;
    const float* asrc = (c < 4) ? v_fea : t_emb;
    const int col0 = (c & 3) * 32;
#pragma unroll
    for (int g = 0; g < 4; g++) {
        int idx = g * 256 + tid;
        int row = idx >> 3, seg = idx & 7;
        uint32_t szA = (m0 + row < NN) ? 16u : 0u;
        cp16z(stgA + row * ROWF + seg * 16,
              asrc + (size_t)(m0 + row) * DD + col0 + seg * 4, szA);
    }
    const uint32_t wH = sbase + F16_BASE + (c % 3) * STAGE_F16 + ABUF_SZ;
    const uint32_t wL = wH + WBUF_SZ;
    {
        int row = tid >> 2, seg = tid & 3;      // 64 rows x 4 16B-segs
        cp16(wH + row * ROWB + seg * 16,
             g_Whi16 + (size_t)(n0 + row) * TWO_D + c * 32 + seg * 8);
        cp16(wL + row * ROWB + seg * 16,
             g_Wlo16 + (size_t)(n0 + row) * TWO_D + c * 32 + seg * 8);
    }
    cp_commit();
}

__device__ __forceinline__ void convert_chunk(char* smemc, int c, int tid) {
    const char* stg = smemc + (c & 1) * STGA_SZ;
    char* af = smemc + F16_BASE + (c % 3) * STAGE_F16;
    const int row = tid >> 1;
    const int c0 = (tid & 1) * 16;
#pragma unroll
    for (int i = 0; i < 4; i++) {
        const int cc = c0 + i * 4;
        float4 x = *(const float4*)(stg + row * ROWF + cc * 4);
        __half2 h01 = __floats2half2_rn(x.x, x.y);
        __half2 h23 = __floats2half2_rn(x.z, x.w);
        *(uint2*)(af + row * ROWB + cc * 2) =
            make_uint2(*(uint32_t*)&h01, *(uint32_t*)&h23);
    }
}

__global__ void __launch_bounds__(256, 2) wq_gemm_fused(const float* __restrict__ v_fea,
                                                        const float* __restrict__ t_emb) {
    extern __shared__ char smem[];
    const uint32_t sbase = smem_u32(smem);
    const int tid = threadIdx.x;
    const int lane = tid & 31, w = tid >> 5;
    const int wm = w >> 1, wn = w & 1;
    const int m0 = blockIdx.y * 128;
    const int n0 = blockIdx.x * 64;

    float acc[2][4][4];
#pragma unroll
    for (int i = 0; i < 2; i++)
#pragma unroll
        for (int j = 0; j < 4; j++)
#pragma unroll
            for (int q = 0; q < 4; q++) acc[i][j][q] = 0.f;

    load_chunk(sbase, 0, m0, n0, v_fea, t_emb, tid);
    load_chunk(sbase, 1, m0, n0, v_fea, t_emb, tid);
    asm volatile("cp.async.wait_group 1;" ::: "memory");
    __syncthreads();
    convert_chunk(smem, 0, tid);

    for (int c = 0; c < 8; c++) {
        if (c + 1 < 8)
            asm volatile("cp.async.wait_group 0;" ::: "memory");
        __syncthreads();
        if (c + 1 < 8) convert_chunk(smem, c + 1, tid);
        if (c + 2 < 8) load_chunk(sbase, c + 2, m0, n0, v_fea, t_emb, tid);

        const uint32_t aF = sbase + F16_BASE + (c % 3) * STAGE_F16;
        const uint32_t bH = aF + ABUF_SZ;
        const uint32_t bL = bH + WBUF_SZ;

#pragma unroll
        for (int ks = 0; ks < 2; ks++) {
            uint32_t afr[2][4], bfh[2][4], bfl[2][4];
#pragma unroll
            for (int mi = 0; mi < 2; mi++) {
                int row = wm * 32 + mi * 16 + (lane & 15);
                uint32_t o = row * ROWB + ks * 32 + ((lane >> 4) << 4);
                ldsm_x4(afr[mi], aF + o);
            }
#pragma unroll
            for (int nj2 = 0; nj2 < 2; nj2++) {
                int row = wn * 32 + nj2 * 16 + (lane & 15);
                uint32_t o = row * ROWB + ks * 32 + ((lane >> 4) << 4);
                ldsm_x4(bfh[nj2], bH + o);
                ldsm_x4(bfl[nj2], bL + o);
            }
#pragma unroll
            for (int mi = 0; mi < 2; mi++)
#pragma unroll
                for (int nj = 0; nj < 4; nj++) {
                    uint32_t bh0 = bfh[nj >> 1][nj & 1], bh1 = bfh[nj >> 1][2 + (nj & 1)];
                    uint32_t bl0 = bfl[nj >> 1][nj & 1], bl1 = bfl[nj >> 1][2 + (nj & 1)];
                    mma16816h(acc[mi][nj], afr[mi], bh0, bh1);   // A * Whi
                    mma16816h(acc[mi][nj], afr[mi], bl0, bl1);   // A * Wlo
                }
        }
    }

    const int gid = lane >> 2, tig = lane & 3;
#pragma unroll
    for (int mi = 0; mi < 2; mi++) {
        int mrow = m0 + wm * 32 + mi * 16 + gid;
#pragma unroll
        for (int nj = 0; nj < 4; nj++) {
            int col = n0 + wn * 32 + nj * 8 + tig * 2;
            if (mrow < NN)
                *(float2*)(g_wq + (size_t)mrow * TWO_D + col) =
                    make_float2(acc[mi][nj][0], acc[mi][nj][1]);
            if (mrow + 8 < NN)
                *(float2*)(g_wq + (size_t)(mrow + 8) * TWO_D + col) =
                    make_float2(acc[mi][nj][2], acc[mi][nj][3]);
        }
    }
}

// ---------------------------------------------------------------------------
// Kernel 2: edge attention — SINGLE online-softmax chain (lightest register
// body, R2 style) + __launch_bounds__(256,6) -> <=40 regs -> 48 warps/SM.
// ---------------------------------------------------------------------------
__global__ void __launch_bounds__(256, 6) edge_attn(const float* __restrict__ v_fea,
                                                    const float* __restrict__ t_emb,
                                                    const int* __restrict__ ef,
                                                    float* __restrict__ out) {
    const int warp = (blockIdx.x * blockDim.x + threadIdx.x) >> 5;
    const int lane = threadIdx.x & 31;
    if (warp >= NN) return;

    const float* wqr = g_wq + (size_t)warp * TWO_D;
    const float4 wqa = *(const float4*)(wqr + lane * 4);
    const float4 wqb = *(const float4*)(wqr + DD + lane * 4);

    const int e_mine = ef[(size_t)warp * KK + lane];

    float m = -INFINITY;
    float s = 0.f;
    float4 acc = make_float4(0.f, 0.f, 0.f, 0.f);

#pragma unroll 4
    for (int k = 0; k < KK; k++) {
        int e = __shfl_sync(0xffffffffu, e_mine, k);
        const float4 v = *(const float4*)(v_fea + (size_t)e * DD + lane * 4);
        const float4 t = *(const float4*)(t_emb + (size_t)e * DD + lane * 4);

        float p = v.x * wqa.x + v.y * wqa.y + v.z * wqa.z + v.w * wqa.w
                + t.x * wqb.x + t.y * wqb.y + t.z * wqb.z + t.w * wqb.w;
        p += __shfl_xor_sync(0xffffffffu, p, 16);
        p += __shfl_xor_sync(0xffffffffu, p, 8);
        p += __shfl_xor_sync(0xffffffffu, p, 4);
        p += __shfl_xor_sync(0xffffffffu, p, 2);
        p += __shfl_xor_sync(0xffffffffu, p, 1);

        float mn = fmaxf(m, p);
        float c = __expf(m - mn);
        float wgt = __expf(p - mn);
        s = s * c + wgt;
        acc.x = acc.x * c + wgt * v.x;
        acc.y = acc.y * c + wgt * v.y;
        acc.z = acc.z * c + wgt * v.z;
        acc.w = acc.w * c + wgt * v.w;
        m = mn;
    }

    const float inv = 1.f / s;
    float4 o = make_float4(acc.x * inv, acc.y * inv, acc.z * inv, acc.w * inv);
    *(float4*)(out + (size_t)warp * DD + lane * 4) = o;
}

// ---------------------------------------------------------------------------
extern "C" void kernel_launch(void* const* d_in, const int* in_sizes, int n_in,
                              void* d_out, int out_size) {
    const float* v_fea = (const float*)d_in[0];
    const float* t_emb = (const float*)d_in[1];
    const int* ef = (const int*)d_in[2];
    const float* W = (const float*)d_in[3];
    float* out = (float*)d_out;

    cudaFuncSetAttribute(wq_gemm_fused, cudaFuncAttributeMaxDynamicSharedMemorySize, GEMM_SMEM);

    w_split<<<TWO_D * TWO_D / 4 / 256, 256>>>(W);
    wq_gemm_fused<<<dim3(TWO_D / 64, MP / 128), 256, GEMM_SMEM>>>(v_fea, t_emb);
    edge_attn<<<(NN + 7) / 8, 256>>>(v_fea, t_emb, ef, out);
}